// round 2
// baseline (speedup 1.0000x reference)
#include <cuda_runtime.h>

#define WARM_UP 365
#define NPHY    12
#define NMUL    4
#define LENF    15
#define MAX_T   2000
#define MAX_G   4000

// Scratch (allocation-free per harness rules)
__device__ float g_qs[MAX_T * MAX_G];     // [t][g] q averaged over NMUL
__device__ float g_w [LENF * MAX_G];      // [k][g] normalized routing weights

__device__ __forceinline__ float fast_lg2(float x) {
    float r;
    asm("lg2.approx.f32 %0, %1;" : "=f"(r) : "f"(x));
    return r;
}
__device__ __forceinline__ float fast_ex2(float x) {
    float r;
    asm("ex2.approx.f32 %0, %1;" : "=f"(r) : "f"(x));
    return r;
}

// ---------------------------------------------------------------------------
// Kernel 1: HBV state scan. One thread per (g, m). Lanes 4j..4j+3 share g.
// ---------------------------------------------------------------------------
__global__ __launch_bounds__(128)
void hbv_scan_kernel(const float* __restrict__ x_phy,
                     const float* __restrict__ params,
                     int T, int G)
{
    int tid = blockIdx.x * blockDim.x + threadIdx.x;
    int g = tid >> 2;
    int m = tid & 3;
    if (g >= G) return;

    const float lb[NPHY] = {1.0f, 50.0f, 0.05f, 0.01f, 0.001f, 0.2f,
                            0.0f, 0.0f, -2.5f, 0.5f, 0.0f, 0.0f};
    const float ub[NPHY] = {6.0f, 1000.0f, 0.9f, 0.5f, 0.2f, 1.0f,
                            10.0f, 100.0f, 2.5f, 10.0f, 0.1f, 0.2f};

    const float* pp = params + (size_t)g * (NPHY * NMUL + 2);
    float phy[NPHY];
#pragma unroll
    for (int i = 0; i < NPHY; i++)
        phy[i] = lb[i] + pp[i * NMUL + m] * (ub[i] - lb[i]);

    const float beta  = phy[0];
    const float fc    = phy[1];
    const float k0    = phy[2];
    const float k1    = phy[3];
    const float k2    = phy[4];
    const float lp    = phy[5];
    const float perc  = phy[6];
    const float uzl   = phy[7];
    const float tt    = phy[8];
    const float cfmax = phy[9];
    const float cfr   = phy[10];
    const float cwh   = phy[11];

    const float inv_fc     = 1.0f / fc;
    const float inv_lpfc   = 1.0f / (lp * fc);
    const float cfr_cfmax  = cfr * cfmax;

    float snowpack = 0.001f, meltwater = 0.001f, sm = 0.001f;
    float suz = 0.001f, slz = 0.001f;

    const float* xg = x_phy + (size_t)g * 3;
    const size_t stride = (size_t)G * 3;

    // software-pipelined forcing
    float Pt = xg[0], Tt = xg[1], PEt = xg[2];

#pragma unroll 2
    for (int t = 0; t < T; t++) {
        // prefetch next step forcing (state-independent)
        float Pn = 0.0f, Tn = 0.0f, PEn = 0.0f;
        if (t + 1 < T) {
            const float* xn = xg + (size_t)(t + 1) * stride;
            Pn = xn[0]; Tn = xn[1]; PEn = xn[2];
        }

        // --- state-independent forcing terms ---
        float rain, snow;
        if (Tt >= tt) { rain = Pt; snow = 0.0f; }
        else          { rain = 0.0f; snow = Pt; }
        float melt_cap = fmaxf(cfmax * (Tt - tt), 0.0f);
        float refr_cap = fmaxf(cfr_cfmax * (tt - Tt), 0.0f);

        // --- soil wetness: depends only on carried sm, start early ---
        float sw = fast_ex2(beta * fast_lg2(sm * inv_fc));
        sw = fminf(sw, 1.0f);

        // --- snow module ---
        snowpack += snow;
        float melt = fminf(melt_cap, snowpack);
        meltwater += melt;
        snowpack  -= melt;
        float refreeze = fminf(refr_cap, meltwater);
        snowpack  += refreeze;
        meltwater -= refreeze;
        float tosoil = fmaxf(meltwater - cwh * snowpack, 0.0f);
        meltwater -= tosoil;

        // --- soil module ---
        float inflow   = rain + tosoil;
        float recharge = inflow * sw;
        sm = sm + inflow - recharge;
        float excess = fmaxf(sm - fc, 0.0f);
        sm -= excess;
        float evap  = fminf(sm * inv_lpfc, 1.0f);
        float etact = fminf(sm, PEt * evap);
        sm = fmaxf(sm - etact, 1e-5f);

        // --- response routing ---
        suz = suz + recharge + excess;
        float prc = fminf(suz, perc);
        suz -= prc;
        float q0 = k0 * fmaxf(suz - uzl, 0.0f);
        suz -= q0;
        float q1 = k1 * suz;
        suz -= q1;
        slz += prc;
        float q2 = k2 * slz;
        slz -= q2;

        float q = q0 + q1 + q2;
        // mean over the 4 m-lanes sharing this g
        q += __shfl_xor_sync(0xffffffffu, q, 1);
        q += __shfl_xor_sync(0xffffffffu, q, 2);
        if (m == 0)
            g_qs[(size_t)t * G + g] = q * 0.25f;

        Pt = Pn; Tt = Tn; PEt = PEn;
    }
}

// ---------------------------------------------------------------------------
// Kernel 2: normalized gamma routing weights per grid cell.
// Gamma normalizer Γ(aa)·th^aa cancels under w / w.sum(0).
// ---------------------------------------------------------------------------
__global__ __launch_bounds__(128)
void hbv_w_kernel(const float* __restrict__ params, int G)
{
    int g = blockIdx.x * blockDim.x + threadIdx.x;
    if (g >= G) return;
    const float* pp = params + (size_t)g * (NPHY * NMUL + 2);
    float a  = pp[NPHY * NMUL + 0] * 2.9f;
    float b  = pp[NPHY * NMUL + 1] * 6.5f;
    float aa = fmaxf(a, 0.0f) + 0.1f;
    float th = fmaxf(b, 0.0f) + 0.5f;
    float inv_th = 1.0f / th;

    float w[LENF];
    float s = 0.0f;
#pragma unroll
    for (int k = 0; k < LENF; k++) {
        float tg = (float)k + 0.5f;
        float v = expf((aa - 1.0f) * logf(tg) - tg * inv_th);
        w[k] = v;
        s += v;
    }
    float inv_s = 1.0f / s;
#pragma unroll
    for (int k = 0; k < LENF; k++)
        g_w[k * MAX_G + g] = w[k] * inv_s;
}

// ---------------------------------------------------------------------------
// Kernel 3: causal 15-tap convolution; outputs rows t in [WARM_UP, T).
// Thread = (g, tile of TS output rows), rolling register window.
// ---------------------------------------------------------------------------
#define TS 16
__global__ __launch_bounds__(256)
void hbv_conv_kernel(float* __restrict__ out, int T, int G)
{
    int g = blockIdx.x * blockDim.x + threadIdx.x;
    if (g >= G) return;
    int t0 = WARM_UP + blockIdx.y * TS;     // first absolute t of this tile

    float w[LENF];
#pragma unroll
    for (int k = 0; k < LENF; k++)
        w[k] = g_w[k * MAX_G + g];

    // window holds q[t-14 .. t-1]; t0 >= WARM_UP >= 14 so always valid
    float qb[LENF - 1];
#pragma unroll
    for (int j = 0; j < LENF - 1; j++)
        qb[j] = g_qs[(size_t)(t0 - (LENF - 1) + j) * G + g];

#pragma unroll
    for (int i = 0; i < TS; i++) {
        int t = t0 + i;
        if (t >= T) break;
        float qt = g_qs[(size_t)t * G + g];
        float acc = qt * w[0];
#pragma unroll
        for (int k = 1; k < LENF; k++)
            acc += qb[LENF - 1 - k] * w[k];
#pragma unroll
        for (int j = 0; j < LENF - 2; j++)
            qb[j] = qb[j + 1];
        qb[LENF - 2] = qt;
        out[(size_t)(t - WARM_UP) * G + g] = acc;
    }
}

// ---------------------------------------------------------------------------
extern "C" void kernel_launch(void* const* d_in, const int* in_sizes, int n_in,
                              void* d_out, int out_size)
{
    // x_phy is the big input (T*G*3), parameters the small one (G*50).
    int ix = 0, ip = 1;
    if (in_sizes[0] < in_sizes[1]) { ix = 1; ip = 0; }
    const float* x_phy  = (const float*)d_in[ix];
    const float* params = (const float*)d_in[ip];
    float* out = (float*)d_out;

    int G = in_sizes[ip] / (NPHY * NMUL + 2);
    int T = in_sizes[ix] / (3 * G);

    int total = G * NMUL;
    hbv_scan_kernel<<<(total + 127) / 128, 128>>>(x_phy, params, T, G);
    hbv_w_kernel<<<(G + 127) / 128, 128>>>(params, G);
    dim3 gconv((G + 255) / 256, (T - WARM_UP + TS - 1) / TS);
    hbv_conv_kernel<<<gconv, 256>>>(out, T, G);
}

// round 4
// speedup vs baseline: 3.1642x; 3.1642x over previous
#include <cuda_runtime.h>
#include <cstdint>

#define WARM_UP 365
#define NPHY    12
#define NMUL    4
#define LENF    15
#define MAX_T   2000
#define MAX_G   4000
#define CHUNK   40
#define GPB     32                 // grid cells per block
#define THREADS (GPB * NMUL)      // 128

// Scratch (allocation-free per harness rules)
__device__ float g_qs4[(size_t)MAX_T * MAX_G * NMUL];  // [t][g*4+m]
__device__ float g_w[LENF * MAX_G];                    // [k][g]

__device__ __forceinline__ float fast_lg2(float x) {
    float r; asm("lg2.approx.f32 %0, %1;" : "=f"(r) : "f"(x)); return r;
}
__device__ __forceinline__ float fast_ex2(float x) {
    float r; asm("ex2.approx.f32 %0, %1;" : "=f"(r) : "f"(x)); return r;
}
__device__ __forceinline__ uint32_t smem_u32(const void* p) {
    return (uint32_t)__cvta_generic_to_shared(p);
}

// Issue async copy of one forcing chunk: CHUNK rows x (GPB*3) floats.
__device__ __forceinline__ void issue_chunk(float (*sb)[GPB * 3],
                                            const float* __restrict__ gsrc,
                                            int t0, int T, int row, int tidx)
{
    const int NV4 = CHUNK * (GPB * 3 / 4);   // 16B packets per chunk
#pragma unroll 2
    for (int idx = tidx; idx < NV4; idx += THREADS) {
        int i = idx / (GPB * 3 / 4);
        int j = idx % (GPB * 3 / 4);
        int t = t0 + i;
        if (t >= T) t = T - 1;               // clamp; data unused
        const float* src = gsrc + (size_t)t * row + j * 4;
        uint32_t dst = smem_u32(&sb[i][j * 4]);
        asm volatile("cp.async.cg.shared.global [%0], [%1], 16;"
                     :: "r"(dst), "l"(src));
    }
    asm volatile("cp.async.commit_group;");
}

// ---------------------------------------------------------------------------
// Kernel 1: HBV scan. Thread = (g, m). Forcing staged via double-buffered
// cp.async through shared memory; q stored per-thread (coalesced 128B/warp).
// ---------------------------------------------------------------------------
__global__ __launch_bounds__(THREADS)
void hbv_scan_kernel(const float* __restrict__ x_phy,
                     const float* __restrict__ params,
                     int T, int G)
{
    __shared__ float sbuf[2][CHUNK][GPB * 3];

    const int tidx = threadIdx.x;
    const int gl   = tidx >> 2;          // local g
    const int m    = tidx & 3;
    const int g    = blockIdx.x * GPB + gl;
    const bool active = (g < G);

    const float lb[NPHY] = {1.0f, 50.0f, 0.05f, 0.01f, 0.001f, 0.2f,
                            0.0f, 0.0f, -2.5f, 0.5f, 0.0f, 0.0f};
    const float ub[NPHY] = {6.0f, 1000.0f, 0.9f, 0.5f, 0.2f, 1.0f,
                            10.0f, 100.0f, 2.5f, 10.0f, 0.1f, 0.2f};

    float phy[NPHY];
#pragma unroll
    for (int i = 0; i < NPHY; i++) phy[i] = 0.5f;   // safe defaults
    if (active) {
        const float* pp = params + (size_t)g * (NPHY * NMUL + 2);
#pragma unroll
        for (int i = 0; i < NPHY; i++)
            phy[i] = lb[i] + pp[i * NMUL + m] * (ub[i] - lb[i]);
    }
    const float beta  = phy[0],  fc    = phy[1],  k0  = phy[2];
    const float k1    = phy[3],  k2    = phy[4],  lp  = phy[5];
    const float perc  = phy[6],  uzl   = phy[7],  tt  = phy[8];
    const float cfmax = phy[9],  cfr   = phy[10], cwh = phy[11];

    const float inv_fc    = 1.0f / fc;
    const float inv_lpfc  = 1.0f / (lp * fc);
    const float cfr_cfmax = cfr * cfmax;

    float snowpack = 0.001f, meltwater = 0.001f, sm = 0.001f;
    float suz = 0.001f, slz = 0.001f;

    const int row = G * 3;
    const float* gsrc = x_phy + (size_t)blockIdx.x * (GPB * 3);
    const int strideQ = G * NMUL;
    const int gm = (g << 2) | m;

    issue_chunk(sbuf[0], gsrc, 0, T, row, tidx);
    asm volatile("cp.async.wait_group 0;");
    __syncthreads();

    const int nchunks = (T + CHUNK - 1) / CHUNK;
    int cur = 0;
    for (int c = 0; c < nchunks; c++) {
        const int t0 = c * CHUNK;
        const bool has_next = (c + 1 < nchunks);
        if (has_next)
            issue_chunk(sbuf[cur ^ 1], gsrc, t0 + CHUNK, T, row, tidx);

#pragma unroll 2
        for (int i = 0; i < CHUNK; i++) {
            const float* f = &sbuf[cur][i][gl * 3];
            float Pt = f[0], Tt = f[1], PEt = f[2];

            // soil wetness: depends only on carried sm, start MUFU early
            float sw = fast_ex2(beta * fast_lg2(sm * inv_fc));
            sw = fminf(sw, 1.0f);

            // forcing-derived (state-independent)
            float rain, snow;
            if (Tt >= tt) { rain = Pt; snow = 0.0f; }
            else          { rain = 0.0f; snow = Pt; }
            float melt_cap = fmaxf(cfmax * (Tt - tt), 0.0f);
            float refr_cap = fmaxf(cfr_cfmax * (tt - Tt), 0.0f);

            // snow module
            snowpack += snow;
            float melt = fminf(melt_cap, snowpack);
            meltwater += melt;
            snowpack  -= melt;
            float refreeze = fminf(refr_cap, meltwater);
            snowpack  += refreeze;
            meltwater -= refreeze;
            float tosoil = fmaxf(meltwater - cwh * snowpack, 0.0f);
            meltwater -= tosoil;

            // soil module
            float inflow   = rain + tosoil;
            float recharge = inflow * sw;
            sm = sm + inflow - recharge;
            float excess = fmaxf(sm - fc, 0.0f);
            sm -= excess;
            float evap  = fminf(sm * inv_lpfc, 1.0f);
            float etact = fminf(sm, PEt * evap);
            sm = fmaxf(sm - etact, 1e-5f);

            // response routing
            suz = suz + recharge + excess;
            float prc = fminf(suz, perc);
            suz -= prc;
            float q0 = k0 * fmaxf(suz - uzl, 0.0f);
            suz -= q0;
            float q1 = k1 * suz;
            suz -= q1;
            slz += prc;
            float q2 = k2 * slz;
            slz -= q2;

            int t = t0 + i;
            if (active && t < T)
                g_qs4[(size_t)t * strideQ + gm] = q0 + q1 + q2;
        }

        if (has_next)
            asm volatile("cp.async.wait_group 0;");
        __syncthreads();
        cur ^= 1;
    }
}

// ---------------------------------------------------------------------------
// Kernel 2: normalized gamma routing weights per grid cell.
// Gamma normalizer Γ(aa)·th^aa cancels under w / w.sum(0).
// ---------------------------------------------------------------------------
__global__ __launch_bounds__(128)
void hbv_w_kernel(const float* __restrict__ params, int G)
{
    int g = blockIdx.x * blockDim.x + threadIdx.x;
    if (g >= G) return;
    const float* pp = params + (size_t)g * (NPHY * NMUL + 2);
    float a  = pp[NPHY * NMUL + 0] * 2.9f;
    float b  = pp[NPHY * NMUL + 1] * 6.5f;
    float aa = fmaxf(a, 0.0f) + 0.1f;
    float th = fmaxf(b, 0.0f) + 0.5f;
    float inv_th = 1.0f / th;

    float w[LENF];
    float s = 0.0f;
#pragma unroll
    for (int k = 0; k < LENF; k++) {
        float tg = (float)k + 0.5f;
        float v = expf((aa - 1.0f) * logf(tg) - tg * inv_th);
        w[k] = v;
        s += v;
    }
    float inv_s = 1.0f / s;
#pragma unroll
    for (int k = 0; k < LENF; k++)
        g_w[k * MAX_G + g] = w[k] * inv_s;
}

// ---------------------------------------------------------------------------
// Kernel 3: mean over NMUL (float4) + causal 15-tap conv; rolling window.
// ---------------------------------------------------------------------------
#define TS 16
__global__ __launch_bounds__(256)
void hbv_conv_kernel(float* __restrict__ out, int T, int G)
{
    int g = blockIdx.x * blockDim.x + threadIdx.x;
    if (g >= G) return;
    int t0 = WARM_UP + blockIdx.y * TS;

    const float4* q4 = (const float4*)g_qs4;   // index t*G + g

    float w[LENF];
#pragma unroll
    for (int k = 0; k < LENF; k++)
        w[k] = g_w[k * MAX_G + g];

    float qb[LENF - 1];
#pragma unroll
    for (int j = 0; j < LENF - 1; j++) {
        float4 v = q4[(size_t)(t0 - (LENF - 1) + j) * G + g];
        qb[j] = 0.25f * (v.x + v.y + v.z + v.w);
    }

#pragma unroll
    for (int i = 0; i < TS; i++) {
        int t = t0 + i;
        if (t >= T) break;
        float4 v = q4[(size_t)t * G + g];
        float qt = 0.25f * (v.x + v.y + v.z + v.w);
        float acc = qt * w[0];
#pragma unroll
        for (int k = 1; k < LENF; k++)
            acc += qb[LENF - 1 - k] * w[k];
#pragma unroll
        for (int j = 0; j < LENF - 2; j++)
            qb[j] = qb[j + 1];
        qb[LENF - 2] = qt;
        out[(size_t)(t - WARM_UP) * G + g] = acc;
    }
}

// ---------------------------------------------------------------------------
extern "C" void kernel_launch(void* const* d_in, const int* in_sizes, int n_in,
                              void* d_out, int out_size)
{
    int ix = 0, ip = 1;
    if (in_sizes[0] < in_sizes[1]) { ix = 1; ip = 0; }
    const float* x_phy  = (const float*)d_in[ix];
    const float* params = (const float*)d_in[ip];
    float* out = (float*)d_out;

    int G = in_sizes[ip] / (NPHY * NMUL + 2);
    int T = in_sizes[ix] / (3 * G);

    hbv_scan_kernel<<<(G + GPB - 1) / GPB, THREADS>>>(x_phy, params, T, G);
    hbv_w_kernel<<<(G + 127) / 128, 128>>>(params, G);
    dim3 gconv((G + 255) / 256, (T - WARM_UP + TS - 1) / TS);
    hbv_conv_kernel<<<gconv, 256>>>(out, T, G);
}

// round 5
// speedup vs baseline: 3.2634x; 1.0313x over previous
#include <cuda_runtime.h>
#include <cstdint>

#define WARM_UP 365
#define NPHY    12
#define NMUL    4
#define LENF    15
#define MAX_T   2000
#define MAX_G   4000
#define CHUNK   40
#define GPB     32                 // grid cells per block
#define THREADS (GPB * NMUL)       // 128

// Scratch (allocation-free per harness rules)
__device__ float g_qs[(size_t)MAX_T * MAX_G];   // [t][g], averaged over NMUL
__device__ float g_w[LENF * MAX_G];             // [k][g]

__device__ __forceinline__ float fast_lg2(float x) {
    float r; asm("lg2.approx.f32 %0, %1;" : "=f"(r) : "f"(x)); return r;
}
__device__ __forceinline__ float fast_ex2(float x) {
    float r; asm("ex2.approx.f32 %0, %1;" : "=f"(r) : "f"(x)); return r;
}
__device__ __forceinline__ uint32_t smem_u32(const void* p) {
    return (uint32_t)__cvta_generic_to_shared(p);
}

// ---------------------------------------------------------------------------
// Kernel 1: HBV scan. Thread = (g, m). Double-buffered cp.async forcing,
// step-level software pipelining of all state-independent terms.
// ---------------------------------------------------------------------------
__global__ __launch_bounds__(THREADS)
void hbv_scan_kernel(const float* __restrict__ x_phy,
                     const float* __restrict__ params,
                     int T, int G)
{
    // +1 padding row so the steady-state prefetch of row i+1 never goes OOB
    __shared__ float sbuf[2][CHUNK + 1][GPB * 3];

    const int tidx = threadIdx.x;
    const int gl   = tidx >> 2;
    const int m    = tidx & 3;
    const int g    = blockIdx.x * GPB + gl;
    const bool active = (g < G);

    const float lb[NPHY] = {1.0f, 50.0f, 0.05f, 0.01f, 0.001f, 0.2f,
                            0.0f, 0.0f, -2.5f, 0.5f, 0.0f, 0.0f};
    const float ub[NPHY] = {6.0f, 1000.0f, 0.9f, 0.5f, 0.2f, 1.0f,
                            10.0f, 100.0f, 2.5f, 10.0f, 0.1f, 0.2f};

    float phy[NPHY];
#pragma unroll
    for (int i = 0; i < NPHY; i++) phy[i] = 0.5f;
    if (active) {
        const float* pp = params + (size_t)g * (NPHY * NMUL + 2);
#pragma unroll
        for (int i = 0; i < NPHY; i++)
            phy[i] = lb[i] + pp[i * NMUL + m] * (ub[i] - lb[i]);
    }
    const float beta  = phy[0],  fc    = phy[1],  k0  = phy[2];
    const float k1    = phy[3],  k2    = phy[4],  lp  = phy[5];
    const float perc  = phy[6],  uzl   = phy[7],  tt  = phy[8];
    const float cfmax = phy[9],  cfr   = phy[10], cwh = phy[11];

    const float inv_fc    = 1.0f / fc;
    const float inv_lpfc  = 1.0f / (lp * fc);
    const float cfr_cfmax = cfr * cfmax;

    float snowpack = 0.001f, meltwater = 0.001f, sm = 0.001f;
    float suz = 0.001f, slz = 0.001f;

    const int row = G * 3;
    const float* gsrc = x_phy + (size_t)blockIdx.x * (GPB * 3);
    const int fbase = gl * 3;

    // ---- async copy of one forcing chunk ----
    auto issue_chunk = [&](int buf, int t0) {
        const int PK = GPB * 3 / 4;          // 16B packets per row (24)
        const int NV4 = CHUNK * PK;
#pragma unroll 2
        for (int idx = tidx; idx < NV4; idx += THREADS) {
            int i = idx / PK;
            int j = idx - i * PK;
            int t = t0 + i;
            if (t >= T) t = T - 1;
            const float* src = gsrc + (size_t)t * row + j * 4;
            uint32_t dst = smem_u32(&sbuf[buf][i][j * 4]);
            asm volatile("cp.async.cg.shared.global [%0], [%1], 16;"
                         :: "r"(dst), "l"(src));
        }
        asm volatile("cp.async.commit_group;");
    };

    issue_chunk(0, 0);
    asm volatile("cp.async.wait_group 0;");
    __syncthreads();

    // ---- pipelined forcing-derived terms for the upcoming step ----
    float rain, snow, melt_cap, refr_cap, PE, PE_li;
    auto make_terms = [&](const float* f) {
        float P  = f[0];
        float Tt = f[1];
        PE       = f[2];
        rain = (Tt >= tt) ? P : 0.0f;
        snow = P - rain;
        melt_cap = fmaxf(cfmax * (Tt - tt), 0.0f);
        refr_cap = fmaxf(cfr_cfmax * (tt - Tt), 0.0f);
        PE_li = PE * inv_lpfc;
    };
    make_terms(&sbuf[0][0][fbase]);

    const int nchunks = (T + CHUNK - 1) / CHUNK;
    int cur = 0;
    for (int c = 0; c < nchunks; c++) {
        const int t0 = c * CHUNK;
        const bool has_next = (c + 1 < nchunks);
        if (has_next)
            issue_chunk(cur ^ 1, t0 + CHUNK);

#pragma unroll 8
        for (int i = 0; i < CHUNK; i++) {
            // ---- soil wetness: MUFU pair straight off carried sm ----
            float sw = fast_ex2(beta * fast_lg2(sm * inv_fc));
            sw = fminf(sw, 1.0f);
            float oms = 1.0f - sw;

            // ---- snow module (inputs already in registers) ----
            float sp1  = snowpack + snow;
            float melt = fminf(melt_cap, sp1);
            float mw1  = meltwater + melt;
            float sp2  = sp1 - melt;
            float refreeze = fminf(refr_cap, mw1);
            float sp3  = sp2 + refreeze;
            float mw2  = mw1 - refreeze;
            float thr  = cwh * sp3;
            float tosoil = fmaxf(mw2 - thr, 0.0f);
            meltwater  = fminf(mw2, thr);
            snowpack   = sp3;

            // ---- soil module (shortened chain) ----
            float inflow   = rain + tosoil;
            float recharge = inflow * sw;
            float sm2 = fmaf(inflow, oms, sm);
            float sm3 = fminf(sm2, fc);
            float excess = sm2 - sm3;
            float pe_evap = fminf(sm3 * PE_li, PE);
            sm = fmaxf(sm3 - pe_evap, 1e-5f);

            // ---- response routing ----
            float suz1 = suz + recharge + excess;
            float suz2 = fmaxf(suz1 - perc, 0.0f);
            float prc  = suz1 - suz2;
            float q0   = k0 * fmaxf(suz2 - uzl, 0.0f);
            float suz3 = suz2 - q0;
            float q1   = k1 * suz3;
            suz = suz3 - q1;
            float slz1 = slz + prc;
            float q2   = k2 * slz1;
            slz = slz1 - q2;

            // ---- prefetch next step's forcing terms (off critical path).
            // Row i+1 == CHUNK reads the padding row; recomputed after swap.
            make_terms(&sbuf[cur][i + 1][fbase]);

            // ---- q mean over m, store by m==0 lanes ----
            float q = q0 + q1 + q2;
            q += __shfl_xor_sync(0xffffffffu, q, 1);
            q += __shfl_xor_sync(0xffffffffu, q, 2);
            int t = t0 + i;
            if (m == 0 && active && t < T)
                g_qs[(size_t)t * G + g] = q * 0.25f;
        }

        if (has_next) {
            asm volatile("cp.async.wait_group 0;");
            __syncthreads();
            cur ^= 1;
            make_terms(&sbuf[cur][0][fbase]);
        }
    }
}

// ---------------------------------------------------------------------------
// Kernel 2: normalized gamma routing weights (Γ(aa)·th^aa cancels).
// ---------------------------------------------------------------------------
__global__ __launch_bounds__(128)
void hbv_w_kernel(const float* __restrict__ params, int G)
{
    int g = blockIdx.x * blockDim.x + threadIdx.x;
    if (g >= G) return;
    const float* pp = params + (size_t)g * (NPHY * NMUL + 2);
    float a  = pp[NPHY * NMUL + 0] * 2.9f;
    float b  = pp[NPHY * NMUL + 1] * 6.5f;
    float aa = fmaxf(a, 0.0f) + 0.1f;
    float th = fmaxf(b, 0.0f) + 0.5f;
    float inv_th = 1.0f / th;

    float w[LENF];
    float s = 0.0f;
#pragma unroll
    for (int k = 0; k < LENF; k++) {
        float tg = (float)k + 0.5f;
        float v = expf((aa - 1.0f) * logf(tg) - tg * inv_th);
        w[k] = v;
        s += v;
    }
    float inv_s = 1.0f / s;
#pragma unroll
    for (int k = 0; k < LENF; k++)
        g_w[k * MAX_G + g] = w[k] * inv_s;
}

// ---------------------------------------------------------------------------
// Kernel 3: causal 15-tap conv on averaged q; rolling register window.
// ---------------------------------------------------------------------------
#define TS 16
__global__ __launch_bounds__(256)
void hbv_conv_kernel(float* __restrict__ out, int T, int G)
{
    int g = blockIdx.x * blockDim.x + threadIdx.x;
    if (g >= G) return;
    int t0 = WARM_UP + blockIdx.y * TS;

    float w[LENF];
#pragma unroll
    for (int k = 0; k < LENF; k++)
        w[k] = g_w[k * MAX_G + g];

    float qb[LENF - 1];
#pragma unroll
    for (int j = 0; j < LENF - 1; j++)
        qb[j] = g_qs[(size_t)(t0 - (LENF - 1) + j) * G + g];

#pragma unroll
    for (int i = 0; i < TS; i++) {
        int t = t0 + i;
        if (t >= T) break;
        float qt = g_qs[(size_t)t * G + g];
        float acc = qt * w[0];
#pragma unroll
        for (int k = 1; k < LENF; k++)
            acc += qb[LENF - 1 - k] * w[k];
#pragma unroll
        for (int j = 0; j < LENF - 2; j++)
            qb[j] = qb[j + 1];
        qb[LENF - 2] = qt;
        out[(size_t)(t - WARM_UP) * G + g] = acc;
    }
}

// ---------------------------------------------------------------------------
extern "C" void kernel_launch(void* const* d_in, const int* in_sizes, int n_in,
                              void* d_out, int out_size)
{
    int ix = 0, ip = 1;
    if (in_sizes[0] < in_sizes[1]) { ix = 1; ip = 0; }
    const float* x_phy  = (const float*)d_in[ix];
    const float* params = (const float*)d_in[ip];
    float* out = (float*)d_out;

    int G = in_sizes[ip] / (NPHY * NMUL + 2);
    int T = in_sizes[ix] / (3 * G);

    hbv_scan_kernel<<<(G + GPB - 1) / GPB, THREADS>>>(x_phy, params, T, G);
    hbv_w_kernel<<<(G + 127) / 128, 128>>>(params, G);
    dim3 gconv((G + 255) / 256, (T - WARM_UP + TS - 1) / TS);
    hbv_conv_kernel<<<gconv, 256>>>(out, T, G);
}

// round 8
// speedup vs baseline: 4.4994x; 1.3788x over previous
#include <cuda_runtime.h>
#include <cstdint>

#define WARM_UP 365
#define NPHY    12
#define NMUL    4
#define LENF    15
#define MAX_T   2000
#define MAX_G   4000
#define CHUNK   40
#define GPB     32                 // grid cells per block
#define THREADS (GPB * NMUL)       // 128

// Scratch (allocation-free per harness rules)
__device__ float g_qs4[(size_t)MAX_T * MAX_G * NMUL];  // [t][g*4+m]
__device__ float g_w[LENF * MAX_G];                    // [k][g]

__device__ __forceinline__ float fast_lg2(float x) {
    float r; asm("lg2.approx.f32 %0, %1;" : "=f"(r) : "f"(x)); return r;
}
__device__ __forceinline__ float fast_ex2(float x) {
    float r; asm("ex2.approx.f32 %0, %1;" : "=f"(r) : "f"(x)); return r;
}
__device__ __forceinline__ uint32_t smem_u32(const void* p) {
    return (uint32_t)__cvta_generic_to_shared(p);
}

// ---------------------------------------------------------------------------
// Kernel 1: HBV scan. Thread = (g, m). Double-buffered cp.async forcing.
// EXACT=true: G % GPB == 0 and T % CHUNK == 0 -> no per-iteration branches.
// ---------------------------------------------------------------------------
template <bool EXACT>
__global__ __launch_bounds__(THREADS)
void hbv_scan_kernel(const float* __restrict__ x_phy,
                     const float* __restrict__ params,
                     int T, int G)
{
    // +1 padding row so the steady-state prefetch of row i+1 never goes OOB
    __shared__ float sbufA[CHUNK + 1][GPB * 3];
    __shared__ float sbufB[CHUNK + 1][GPB * 3];

    const int tidx = threadIdx.x;
    const int gl   = tidx >> 2;
    const int m    = tidx & 3;
    const int g    = blockIdx.x * GPB + gl;
    const bool active = EXACT || (g < G);

    const float lb[NPHY] = {1.0f, 50.0f, 0.05f, 0.01f, 0.001f, 0.2f,
                            0.0f, 0.0f, -2.5f, 0.5f, 0.0f, 0.0f};
    const float ub[NPHY] = {6.0f, 1000.0f, 0.9f, 0.5f, 0.2f, 1.0f,
                            10.0f, 100.0f, 2.5f, 10.0f, 0.1f, 0.2f};

    float phy[NPHY];
#pragma unroll
    for (int i = 0; i < NPHY; i++) phy[i] = 0.5f;
    if (active) {
        const float* pp = params + (size_t)g * (NPHY * NMUL + 2);
#pragma unroll
        for (int i = 0; i < NPHY; i++)
            phy[i] = lb[i] + pp[i * NMUL + m] * (ub[i] - lb[i]);
    }
    const float beta  = phy[0],  fc    = phy[1],  k0  = phy[2];
    const float k1    = phy[3],  k2    = phy[4],  lp  = phy[5];
    const float perc  = phy[6],  uzl   = phy[7],  tt  = phy[8];
    const float cfmax = phy[9],  cfr   = phy[10], cwh = phy[11];

    const float inv_fc    = 1.0f / fc;
    const float inv_lpfc  = 1.0f / (lp * fc);
    const float cfr_cfmax = cfr * cfmax;
    const float blg_ifc   = beta * fast_lg2(inv_fc);   // fold /fc into exponent

    float snowpack = 0.001f, meltwater = 0.001f, sm = 0.001f;
    float suz = 0.001f, slz = 0.001f;

    const int row = G * 3;
    const float* gsrc = x_phy + (size_t)blockIdx.x * (GPB * 3);
    const int fbase = gl * 3;
    const int strideQ = G * NMUL;
    float* qout = g_qs4 + ((g << 2) | m);   // induction pointer, += strideQ/step

    auto issue_chunk = [&](float (*sb)[GPB * 3], int t0) {
        const int PK = GPB * 3 / 4;          // 16B packets per row (24)
        const int NV4 = CHUNK * PK;
#pragma unroll 2
        for (int idx = tidx; idx < NV4; idx += THREADS) {
            int i = idx / PK;
            int j = idx - i * PK;
            int t = t0 + i;
            if (!EXACT && t >= T) t = T - 1;
            const float* src = gsrc + (size_t)t * row + j * 4;
            uint32_t dst = smem_u32(&sb[i][j * 4]);
            asm volatile("cp.async.cg.shared.global [%0], [%1], 16;"
                         :: "r"(dst), "l"(src));
        }
        asm volatile("cp.async.commit_group;");
    };

    issue_chunk(sbufA, 0);
    asm volatile("cp.async.wait_group 0;");
    __syncthreads();

    // pipelined forcing-derived terms for the upcoming step (all off-chain)
    float rain, snow, melt_cap, refr_cap, PE, om_pe;
    auto make_terms = [&](const float* f) {
        float P  = f[0];
        float Tt = f[1];
        PE       = f[2];
        rain = (Tt >= tt) ? P : 0.0f;
        snow = P - rain;
        melt_cap = fmaxf(cfmax * (Tt - tt), 0.0f);
        refr_cap = fmaxf(cfr_cfmax * (tt - Tt), 0.0f);
        om_pe = 1.0f - PE * inv_lpfc;
    };
    make_terms(&sbufA[0][fbase]);

    const int nchunks = (T + CHUNK - 1) / CHUNK;
    float (*cur)[GPB * 3] = sbufA;
    float (*nxt)[GPB * 3] = sbufB;

    for (int c = 0; c < nchunks; c++) {
        const int t0 = c * CHUNK;
        const bool has_next = (c + 1 < nchunks);
        if (has_next)
            issue_chunk(nxt, t0 + CHUNK);

#pragma unroll 8
        for (int i = 0; i < CHUNK; i++) {
            // ---- soil wetness: MUFU pair straight off carried sm ----
            float sw = fast_ex2(fmaf(beta, fast_lg2(sm), blg_ifc));
            sw = fminf(sw, 1.0f);
            float oms = 1.0f - sw;

            // ---- snow module (inputs already in registers) ----
            float sp1  = snowpack + snow;
            float melt = fminf(melt_cap, sp1);
            float mw1  = meltwater + melt;
            float sp2  = sp1 - melt;
            float refreeze = fminf(refr_cap, mw1);
            float sp3  = sp2 + refreeze;
            float mw2  = mw1 - refreeze;
            float thr  = cwh * sp3;
            float tosoil = fmaxf(mw2 - thr, 0.0f);
            meltwater  = fminf(mw2, thr);
            snowpack   = sp3;

            // ---- soil module (shortened chain) ----
            float inflow   = rain + tosoil;
            float recharge = inflow * sw;
            float sm2 = fmaf(inflow, oms, sm);
            float sm3 = fminf(sm2, fc);
            float excess = sm2 - sm3;
            // sm3 - min(sm3*PE_li, PE) == max(sm3*(1-PE_li), sm3-PE)
            sm = fmaxf(fmaxf(sm3 * om_pe, sm3 - PE), 1e-5f);

            // ---- response routing ----
            float suz1 = suz + recharge + excess;
            float suz2 = fmaxf(suz1 - perc, 0.0f);
            float prc  = suz1 - suz2;
            float q0   = k0 * fmaxf(suz2 - uzl, 0.0f);
            float suz3 = suz2 - q0;
            float q1   = k1 * suz3;
            suz = suz3 - q1;
            float slz1 = slz + prc;
            float q2   = k2 * slz1;
            slz = slz1 - q2;

            // ---- prefetch next step's forcing terms (off critical path) ----
            make_terms(&cur[i + 1][fbase]);

            // ---- unconditional coalesced store (no branch in EXACT path) ----
            float q = q0 + q1 + q2;
            if (EXACT) {
                *qout = q;
                qout += strideQ;
            } else {
                int t = t0 + i;
                if (active && t < T)
                    qout[(size_t)(t - t0) * strideQ] = q;
            }
        }
        if (!EXACT)
            qout += (size_t)CHUNK * strideQ;

        if (has_next) {
            asm volatile("cp.async.wait_group 0;");
            __syncthreads();
            float (*tmp)[GPB * 3] = cur; cur = nxt; nxt = tmp;
            make_terms(&cur[0][fbase]);
        }
    }
}

// ---------------------------------------------------------------------------
// Kernel 2: normalized gamma routing weights (Γ(aa)·th^aa cancels).
// ---------------------------------------------------------------------------
__global__ __launch_bounds__(128)
void hbv_w_kernel(const float* __restrict__ params, int G)
{
    int g = blockIdx.x * blockDim.x + threadIdx.x;
    if (g >= G) return;
    const float* pp = params + (size_t)g * (NPHY * NMUL + 2);
    float a  = pp[NPHY * NMUL + 0] * 2.9f;
    float b  = pp[NPHY * NMUL + 1] * 6.5f;
    float aa = fmaxf(a, 0.0f) + 0.1f;
    float th = fmaxf(b, 0.0f) + 0.5f;
    float inv_th = 1.0f / th;

    float w[LENF];
    float s = 0.0f;
#pragma unroll
    for (int k = 0; k < LENF; k++) {
        float tg = (float)k + 0.5f;
        float v = expf((aa - 1.0f) * logf(tg) - tg * inv_th);
        w[k] = v;
        s += v;
    }
    float inv_s = 1.0f / s;
#pragma unroll
    for (int k = 0; k < LENF; k++)
        g_w[k * MAX_G + g] = w[k] * inv_s;
}

// ---------------------------------------------------------------------------
// Kernel 3: mean over NMUL (float4) + causal 15-tap conv; rolling window.
// ---------------------------------------------------------------------------
#define TS 16
__global__ __launch_bounds__(256)
void hbv_conv_kernel(float* __restrict__ out, int T, int G)
{
    int g = blockIdx.x * blockDim.x + threadIdx.x;
    if (g >= G) return;
    int t0 = WARM_UP + blockIdx.y * TS;

    const float4* q4 = (const float4*)g_qs4;   // index t*G + g

    float w[LENF];
#pragma unroll
    for (int k = 0; k < LENF; k++)
        w[k] = g_w[k * MAX_G + g];

    float qb[LENF - 1];
#pragma unroll
    for (int j = 0; j < LENF - 1; j++) {
        float4 v = q4[(size_t)(t0 - (LENF - 1) + j) * G + g];
        qb[j] = 0.25f * (v.x + v.y + v.z + v.w);
    }

#pragma unroll
    for (int i = 0; i < TS; i++) {
        int t = t0 + i;
        if (t >= T) break;
        float4 v = q4[(size_t)t * G + g];
        float qt = 0.25f * (v.x + v.y + v.z + v.w);
        float acc = qt * w[0];
#pragma unroll
        for (int k = 1; k < LENF; k++)
            acc += qb[LENF - 1 - k] * w[k];
#pragma unroll
        for (int j = 0; j < LENF - 2; j++)
            qb[j] = qb[j + 1];
        qb[LENF - 2] = qt;
        out[(size_t)(t - WARM_UP) * G + g] = acc;
    }
}

// ---------------------------------------------------------------------------
extern "C" void kernel_launch(void* const* d_in, const int* in_sizes, int n_in,
                              void* d_out, int out_size)
{
    int ix = 0, ip = 1;
    if (in_sizes[0] < in_sizes[1]) { ix = 1; ip = 0; }
    const float* x_phy  = (const float*)d_in[ix];
    const float* params = (const float*)d_in[ip];
    float* out = (float*)d_out;

    int G = in_sizes[ip] / (NPHY * NMUL + 2);
    int T = in_sizes[ix] / (3 * G);

    int nblk = (G + GPB - 1) / GPB;
    if ((G % GPB) == 0 && (T % CHUNK) == 0)
        hbv_scan_kernel<true><<<nblk, THREADS>>>(x_phy, params, T, G);
    else
        hbv_scan_kernel<false><<<nblk, THREADS>>>(x_phy, params, T, G);

    hbv_w_kernel<<<(G + 127) / 128, 128>>>(params, G);
    dim3 gconv((G + 255) / 256, (T - WARM_UP + TS - 1) / TS);
    hbv_conv_kernel<<<gconv, 256>>>(out, T, G);
}